// round 2
// baseline (speedup 1.0000x reference)
#include <cuda_runtime.h>
#include <stdint.h>

#define N_NODES 50000
#define N_EDGES 800000
#define IN_C    3
#define HID     128
#define OUTC    64

// ---- scratch (device globals; no allocation allowed) ----
__device__ int   g_deg[N_NODES];
__device__ float g_dinv[N_NODES];
__device__ float g_agg1[N_NODES * IN_C];
__device__ float g_h1[N_NODES * HID];
__device__ float g_h2[N_NODES * OUTC];

// 1) zero deg + agg1
__global__ void k_init() {
    int i = blockIdx.x * blockDim.x + threadIdx.x;
    if (i < N_NODES) g_deg[i] = 0;
    if (i < N_NODES * IN_C) g_agg1[i] = 0.0f;
}

// 2) degree histogram on dst (self-loop added analytically later as +1)
__global__ void k_deg(const int* __restrict__ ei) {
    int e = blockIdx.x * blockDim.x + threadIdx.x;
    if (e >= N_EDGES) return;
    int d = ei[N_EDGES + e];
    atomicAdd(&g_deg[d], 1);
}

// 3) dinv = rsqrt(deg + 1)
__global__ void k_dinv() {
    int i = blockIdx.x * blockDim.x + threadIdx.x;
    if (i >= N_NODES) return;
    g_dinv[i] = rsqrtf((float)(g_deg[i] + 1));
}

// 4) layer-1 aggregation in 3-dim input space (scatter-add)
__global__ void k_agg1(const int* __restrict__ ei,
                       const float* __restrict__ x) {
    int e = blockIdx.x * blockDim.x + threadIdx.x;
    if (e >= N_EDGES) return;
    int s = ei[e];
    int d = ei[N_EDGES + e];
    float nrm = g_dinv[s] * g_dinv[d];
    float x0 = __ldg(&x[s * 3 + 0]);
    float x1 = __ldg(&x[s * 3 + 1]);
    float x2 = __ldg(&x[s * 3 + 2]);
    atomicAdd(&g_agg1[d * 3 + 0], x0 * nrm);
    atomicAdd(&g_agg1[d * 3 + 1], x1 * nrm);
    atomicAdd(&g_agg1[d * 3 + 2], x2 * nrm);
}

// 5) h1 = relu( (agg1 + x*dinv^2) @ W1 + b1 )   [N,3]@[3,128]
__global__ void k_h1(const float* __restrict__ x,
                     const float* __restrict__ W1,
                     const float* __restrict__ b1) {
    int idx = blockIdx.x * blockDim.x + threadIdx.x;
    if (idx >= N_NODES * HID) return;
    int node = idx >> 7;
    int j    = idx & (HID - 1);
    float di = g_dinv[node];
    float sl = di * di;
    float v0 = g_agg1[node * 3 + 0] + __ldg(&x[node * 3 + 0]) * sl;
    float v1 = g_agg1[node * 3 + 1] + __ldg(&x[node * 3 + 1]) * sl;
    float v2 = g_agg1[node * 3 + 2] + __ldg(&x[node * 3 + 2]) * sl;
    float h = b1[j];
    h = fmaf(v0, W1[0 * HID + j], h);
    h = fmaf(v1, W1[1 * HID + j], h);
    h = fmaf(v2, W1[2 * HID + j], h);
    g_h1[idx] = fmaxf(h, 0.0f);
}

// 6) h2 = h1 @ W2   [N,128]@[128,64]; smem-tiled, 4-col register blocking
//    block = 256 threads, 16 nodes per block; thread owns (node, 4 cols)
__global__ void __launch_bounds__(256) k_h2(const float* __restrict__ W2) {
    __shared__ float sW2[HID * OUTC];   // 32 KB
    __shared__ float sh1[16 * HID];     // 8 KB
    int tid = threadIdx.x;
    int nodeBase = blockIdx.x * 16;

    #pragma unroll 4
    for (int i = tid; i < HID * OUTC; i += 256) sW2[i] = W2[i];
    #pragma unroll 2
    for (int i = tid; i < 16 * HID; i += 256) sh1[i] = g_h1[nodeBase * HID + i];
    __syncthreads();

    int m  = tid >> 4;          // local node 0..15
    int j0 = (tid & 15) * 4;    // output col group
    const float* hrow = &sh1[m * HID];

    float a0 = 0.f, a1 = 0.f, a2 = 0.f, a3 = 0.f;
    #pragma unroll 8
    for (int k = 0; k < HID; k++) {
        float h = hrow[k];
        float4 w = *(const float4*)&sW2[k * OUTC + j0];
        a0 = fmaf(h, w.x, a0);
        a1 = fmaf(h, w.y, a1);
        a2 = fmaf(h, w.z, a2);
        a3 = fmaf(h, w.w, a3);
    }
    float4 r = make_float4(a0, a1, a2, a3);
    *(float4*)&g_h2[(nodeBase + m) * OUTC + j0] = r;
}

// 7) out = b2 + h2 * dinv^2   (self-loop contribution + bias; initializes d_out)
__global__ void k_outinit(const float* __restrict__ b2,
                          float* __restrict__ out) {
    int idx = blockIdx.x * blockDim.x + threadIdx.x;
    if (idx >= N_NODES * OUTC) return;
    int node = idx >> 6;
    int j    = idx & (OUTC - 1);
    float di = g_dinv[node];
    out[idx] = b2[j] + g_h2[idx] * di * di;
}

// 8) layer-2 aggregation in 64-dim space: 16 threads per edge, float4 red each
__global__ void k_agg2(const int* __restrict__ ei,
                       float* __restrict__ out) {
    int tid = blockIdx.x * blockDim.x + threadIdx.x;
    int e = tid >> 4;
    if (e >= N_EDGES) return;
    int t = tid & 15;
    int s = ei[e];
    int d = ei[N_EDGES + e];
    float nrm = g_dinv[s] * g_dinv[d];
    float4 v = ((const float4*)(g_h2 + (size_t)s * OUTC))[t];
    float4 r = make_float4(v.x * nrm, v.y * nrm, v.z * nrm, v.w * nrm);
    float* p = out + (size_t)d * OUTC + t * 4;
    asm volatile("red.global.add.v4.f32 [%0], {%1,%2,%3,%4};"
                 :: "l"(p), "f"(r.x), "f"(r.y), "f"(r.z), "f"(r.w)
                 : "memory");
}

extern "C" void kernel_launch(void* const* d_in, const int* in_sizes, int n_in,
                              void* d_out, int out_size) {
    const float* x  = (const float*)d_in[0];
    const int*   ei = (const int*)d_in[1];   // jnp.int64 downcast to int32 by JAX default config
    const float* W1 = (const float*)d_in[2];
    const float* b1 = (const float*)d_in[3];
    const float* W2 = (const float*)d_in[4];
    const float* b2 = (const float*)d_in[5];
    float* out = (float*)d_out;

    k_init<<<(N_NODES * IN_C + 255) / 256, 256>>>();
    k_deg<<<(N_EDGES + 255) / 256, 256>>>(ei);
    k_dinv<<<(N_NODES + 255) / 256, 256>>>();
    k_agg1<<<(N_EDGES + 255) / 256, 256>>>(ei, x);
    k_h1<<<(N_NODES * HID + 255) / 256, 256>>>(x, W1, b1);
    k_h2<<<(N_NODES + 15) / 16, 256>>>(W2);
    k_outinit<<<(N_NODES * OUTC + 255) / 256, 256>>>(b2, out);
    k_agg2<<<(N_EDGES * 16 + 255) / 256, 256>>>(ei, out);
}

// round 3
// speedup vs baseline: 1.4420x; 1.4420x over previous
#include <cuda_runtime.h>
#include <stdint.h>

#define N_NODES 50000
#define N_PAD   50048   // padded to multiple of 128 for k_h2 tiling
#define N_EDGES 800000
#define IN_C    3
#define HID     128
#define OUTC    64

// ---- scratch (device globals; no allocation allowed) ----
__device__ int   g_deg[N_NODES];
__device__ float g_dinv[N_NODES];
__device__ __align__(16) float g_agg1[N_NODES * 4];   // stride-4 for v4 RED
__device__ __align__(16) float g_h1[N_PAD * HID];
__device__ __align__(16) float g_h2[N_PAD * OUTC];

// 1) zero deg + agg1
__global__ void k_init() {
    int i = blockIdx.x * blockDim.x + threadIdx.x;
    if (i < N_NODES) g_deg[i] = 0;
    if (i < N_NODES) ((float4*)g_agg1)[i] = make_float4(0.f, 0.f, 0.f, 0.f);
}

// 2) degree histogram on dst (self-loop folded in analytically as +1)
__global__ void k_deg(const int* __restrict__ ei) {
    int e = blockIdx.x * blockDim.x + threadIdx.x;
    if (e >= N_EDGES) return;
    atomicAdd(&g_deg[ei[N_EDGES + e]], 1);
}

// 3) dinv = rsqrt(deg + 1)
__global__ void k_dinv() {
    int i = blockIdx.x * blockDim.x + threadIdx.x;
    if (i >= N_NODES) return;
    g_dinv[i] = rsqrtf((float)(g_deg[i] + 1));
}

// 4) layer-1 aggregation in 3-dim input space: ONE v4 RED per edge
__global__ void k_agg1(const int* __restrict__ ei,
                       const float* __restrict__ x) {
    int e = blockIdx.x * blockDim.x + threadIdx.x;
    if (e >= N_EDGES) return;
    int s = ei[e];
    int d = ei[N_EDGES + e];
    float nrm = g_dinv[s] * g_dinv[d];
    float v0 = __ldg(&x[s * 3 + 0]) * nrm;
    float v1 = __ldg(&x[s * 3 + 1]) * nrm;
    float v2 = __ldg(&x[s * 3 + 2]) * nrm;
    float* p = g_agg1 + (size_t)d * 4;
    asm volatile("red.global.add.v4.f32 [%0], {%1,%2,%3,%4};"
                 :: "l"(p), "f"(v0), "f"(v1), "f"(v2), "f"(0.f)
                 : "memory");
}

// 5) h1 = relu( (agg1 + x*dinv^2) @ W1 + b1 )   [N,3]@[3,128]
__global__ void k_h1(const float* __restrict__ x,
                     const float* __restrict__ W1,
                     const float* __restrict__ b1) {
    int idx = blockIdx.x * blockDim.x + threadIdx.x;
    if (idx >= N_NODES * HID) return;
    int node = idx >> 7;
    int j    = idx & (HID - 1);
    float di = g_dinv[node];
    float sl = di * di;
    float v0 = g_agg1[node * 4 + 0] + __ldg(&x[node * 3 + 0]) * sl;
    float v1 = g_agg1[node * 4 + 1] + __ldg(&x[node * 3 + 1]) * sl;
    float v2 = g_agg1[node * 4 + 2] + __ldg(&x[node * 3 + 2]) * sl;
    float h = b1[j];
    h = fmaf(v0, W1[0 * HID + j], h);
    h = fmaf(v1, W1[1 * HID + j], h);
    h = fmaf(v2, W1[2 * HID + j], h);
    g_h1[idx] = fmaxf(h, 0.0f);
}

// 6) h2 = h1 @ W2 (+ fused: out = b2 + h2*dinv^2)
//    [N,128]@[128,64]; 128 nodes/block, 256 threads.
//    Thread = (node-group g: 8 nodes, col-group c: 4 cols). 32 accumulators.
//    All smem traffic is float4, broadcast/conflict-free. 1.5 B LDS per FMA.
__global__ void __launch_bounds__(256) k_h2(const float* __restrict__ W2,
                                            const float* __restrict__ b2,
                                            float* __restrict__ out) {
    __shared__ float4 sW2[HID * 16];     // [k][16 x float4]  32 KB
    __shared__ float4 sh1[128 * 32];     // [node][32 x float4] 64 KB
    int tid = threadIdx.x;
    int nodeBase = blockIdx.x * 128;

    #pragma unroll 4
    for (int i = tid; i < HID * 16; i += 256) sW2[i] = ((const float4*)W2)[i];
    const float4* gh1 = (const float4*)(g_h1 + (size_t)nodeBase * HID);
    #pragma unroll 8
    for (int i = tid; i < 128 * 32; i += 256) sh1[i] = gh1[i];
    __syncthreads();

    int c  = tid & 15;        // cols 4c..4c+3
    int m0 = (tid >> 4) * 8;  // nodes m0..m0+7 (local)

    float4 acc[8];
    #pragma unroll
    for (int j = 0; j < 8; j++) acc[j] = make_float4(0.f, 0.f, 0.f, 0.f);

    #pragma unroll 2
    for (int kb = 0; kb < HID; kb += 4) {
        float4 w0 = sW2[(kb + 0) * 16 + c];
        float4 w1 = sW2[(kb + 1) * 16 + c];
        float4 w2 = sW2[(kb + 2) * 16 + c];
        float4 w3 = sW2[(kb + 3) * 16 + c];
        #pragma unroll
        for (int j = 0; j < 8; j++) {
            float4 h = sh1[(m0 + j) * 32 + (kb >> 2)];
            acc[j].x = fmaf(h.x, w0.x, fmaf(h.y, w1.x, fmaf(h.z, w2.x, fmaf(h.w, w3.x, acc[j].x))));
            acc[j].y = fmaf(h.x, w0.y, fmaf(h.y, w1.y, fmaf(h.z, w2.y, fmaf(h.w, w3.y, acc[j].y))));
            acc[j].z = fmaf(h.x, w0.z, fmaf(h.y, w1.z, fmaf(h.z, w2.z, fmaf(h.w, w3.z, acc[j].z))));
            acc[j].w = fmaf(h.x, w0.w, fmaf(h.y, w1.w, fmaf(h.z, w2.w, fmaf(h.w, w3.w, acc[j].w))));
        }
    }

    float4 bb = ((const float4*)b2)[c];
    #pragma unroll
    for (int j = 0; j < 8; j++) {
        int node = nodeBase + m0 + j;
        ((float4*)g_h2)[(size_t)node * 16 + c] = acc[j];
        if (node < N_NODES) {
            float di = g_dinv[node];
            float sl = di * di;
            float4 o = make_float4(fmaf(acc[j].x, sl, bb.x),
                                   fmaf(acc[j].y, sl, bb.y),
                                   fmaf(acc[j].z, sl, bb.z),
                                   fmaf(acc[j].w, sl, bb.w));
            ((float4*)out)[(size_t)node * 16 + c] = o;
        }
    }
}

// 7) layer-2 aggregation in 64-dim space: 16 threads/edge, one v4 RED each
__global__ void k_agg2(const int* __restrict__ ei,
                       float* __restrict__ out) {
    int tid = blockIdx.x * blockDim.x + threadIdx.x;
    int e = tid >> 4;
    if (e >= N_EDGES) return;
    int t = tid & 15;
    int s = ei[e];
    int d = ei[N_EDGES + e];
    float nrm = g_dinv[s] * g_dinv[d];
    float4 v = ((const float4*)(g_h2 + (size_t)s * OUTC))[t];
    float* p = out + (size_t)d * OUTC + t * 4;
    asm volatile("red.global.add.v4.f32 [%0], {%1,%2,%3,%4};"
                 :: "l"(p), "f"(v.x * nrm), "f"(v.y * nrm), "f"(v.z * nrm), "f"(v.w * nrm)
                 : "memory");
}

extern "C" void kernel_launch(void* const* d_in, const int* in_sizes, int n_in,
                              void* d_out, int out_size) {
    const float* x  = (const float*)d_in[0];
    const int*   ei = (const int*)d_in[1];   // int64 in ref, int32 on device (JAX x64 disabled)
    const float* W1 = (const float*)d_in[2];
    const float* b1 = (const float*)d_in[3];
    const float* W2 = (const float*)d_in[4];
    const float* b2 = (const float*)d_in[5];
    float* out = (float*)d_out;

    k_init<<<(N_NODES + 255) / 256, 256>>>();
    k_deg<<<(N_EDGES + 255) / 256, 256>>>(ei);
    k_dinv<<<(N_NODES + 255) / 256, 256>>>();
    k_agg1<<<(N_EDGES + 255) / 256, 256>>>(ei, x);
    k_h1<<<(N_NODES * HID + 255) / 256, 256>>>(x, W1, b1);
    k_h2<<<N_PAD / 128, 256>>>(W2, b2, out);
    k_agg2<<<(N_EDGES * 16 + 255) / 256, 256>>>(ei, out);
}

// round 4
// speedup vs baseline: 1.8210x; 1.2628x over previous
#include <cuda_runtime.h>
#include <stdint.h>

#define N_NODES 50000
#define N_PAD   50048   // multiple of 128 for k_h2 tiling
#define N_EDGES 800000
#define HID     128
#define OUTC    64
#define SCAN_BLOCKS 196 // 196*256 = 50176 >= N_NODES

// ---- scratch (device globals; no allocation allowed) ----
__device__ int   g_deg[N_NODES];
__device__ int   g_rowstart[N_NODES];
__device__ int   g_wpos[N_NODES];
__device__ int   g_csrc[N_EDGES];
__device__ int   g_bsum[SCAN_BLOCKS];
__device__ int   g_boff[SCAN_BLOCKS];
__device__ float g_dinv[N_NODES];
__device__ __align__(16) float g_v[N_PAD * 4];      // layer-1 aggregated 3-vec (pad stays 0)
__device__ __align__(16) float g_h2[N_PAD * OUTC];

// 1) zero degrees
__global__ void k_init() {
    int i = blockIdx.x * blockDim.x + threadIdx.x;
    if (i < N_NODES) g_deg[i] = 0;
}

// 2) degree histogram on dst (self-loop folded analytically as +1)
__global__ void k_deg(const int* __restrict__ ei) {
    int e = blockIdx.x * blockDim.x + threadIdx.x;
    if (e >= N_EDGES) return;
    atomicAdd(&g_deg[ei[N_EDGES + e]], 1);
}

// 3a) per-block degree sums
__global__ void k_scan1() {
    __shared__ int s[256];
    int t = threadIdx.x;
    int i = blockIdx.x * 256 + t;
    s[t] = (i < N_NODES) ? g_deg[i] : 0;
    __syncthreads();
    for (int o = 128; o > 0; o >>= 1) {
        if (t < o) s[t] += s[t + o];
        __syncthreads();
    }
    if (t == 0) g_bsum[blockIdx.x] = s[0];
}

// 3b) exclusive scan of block sums (single block)
__global__ void k_scan2() {
    __shared__ int s[256];
    int t = threadIdx.x;
    int v = (t < SCAN_BLOCKS) ? g_bsum[t] : 0;
    s[t] = v;
    __syncthreads();
    for (int o = 1; o < 256; o <<= 1) {
        int x = (t >= o) ? s[t - o] : 0;
        __syncthreads();
        s[t] += x;
        __syncthreads();
    }
    if (t < SCAN_BLOCKS) g_boff[t] = s[t] - v;
}

// 3c) row starts + write cursors + dinv
__global__ void k_scan3() {
    __shared__ int s[256];
    int t = threadIdx.x;
    int i = blockIdx.x * 256 + t;
    int v = (i < N_NODES) ? g_deg[i] : 0;
    s[t] = v;
    __syncthreads();
    for (int o = 1; o < 256; o <<= 1) {
        int x = (t >= o) ? s[t - o] : 0;
        __syncthreads();
        s[t] += x;
        __syncthreads();
    }
    if (i < N_NODES) {
        int rs = g_boff[blockIdx.x] + s[t] - v;
        g_rowstart[i] = rs;
        g_wpos[i] = rs;
        g_dinv[i] = rsqrtf((float)(v + 1));
    }
}

// 4) CSR scatter: src indices grouped by dst
__global__ void k_csr(const int* __restrict__ ei) {
    int e = blockIdx.x * blockDim.x + threadIdx.x;
    if (e >= N_EDGES) return;
    int s = ei[e];
    int d = ei[N_EDGES + e];
    int pos = atomicAdd(&g_wpos[d], 1);
    g_csrc[pos] = s;
}

// 5) layer-1 gather in 3-dim space: warp per node, atomic-free
__global__ void k_gather1(const float* __restrict__ x) {
    int gid = blockIdx.x * blockDim.x + threadIdx.x;
    int node = gid >> 5;
    int lane = gid & 31;
    if (node >= N_NODES) return;
    int row = g_rowstart[node];
    int end = row + g_deg[node];
    float a0 = 0.f, a1 = 0.f, a2 = 0.f;
    for (int e = row + lane; e < end; e += 32) {
        int s = g_csrc[e];
        float w = g_dinv[s];
        a0 = fmaf(__ldg(&x[s * 3 + 0]), w, a0);
        a1 = fmaf(__ldg(&x[s * 3 + 1]), w, a1);
        a2 = fmaf(__ldg(&x[s * 3 + 2]), w, a2);
    }
    #pragma unroll
    for (int o = 16; o > 0; o >>= 1) {
        a0 += __shfl_down_sync(0xffffffff, a0, o);
        a1 += __shfl_down_sync(0xffffffff, a1, o);
        a2 += __shfl_down_sync(0xffffffff, a2, o);
    }
    if (lane == 0) {
        float dd = g_dinv[node];
        float sl = dd * dd;
        float4 v;
        v.x = fmaf(dd, a0, sl * __ldg(&x[node * 3 + 0]));
        v.y = fmaf(dd, a1, sl * __ldg(&x[node * 3 + 1]));
        v.z = fmaf(dd, a2, sl * __ldg(&x[node * 3 + 2]));
        v.w = 0.f;
        ((float4*)g_v)[node] = v;
    }
}

// 6) fused: h1 = relu(v @ W1 + b1) computed into smem, then h2 = h1 @ W2.
//    128 nodes/block, 256 threads; thread = (8 nodes, 4 cols), all-float4 smem.
__global__ void __launch_bounds__(256) k_h2(const float* __restrict__ W1,
                                            const float* __restrict__ b1,
                                            const float* __restrict__ W2) {
    __shared__ float4 sW2[HID * 16];   // 32 KB
    __shared__ float4 sh1[128 * 32];   // 64 KB
    int tid = threadIdx.x;
    int nodeBase = blockIdx.x * 128;

    #pragma unroll 4
    for (int i = tid; i < HID * 16; i += 256) sW2[i] = ((const float4*)W2)[i];

    // fused h1 computation while filling sh1
    #pragma unroll 4
    for (int i = tid; i < 128 * 32; i += 256) {
        int node = i >> 5;
        int q    = i & 31;
        float4 v  = ((const float4*)g_v)[nodeBase + node];
        float4 w0 = __ldg(&((const float4*)W1)[0 * 32 + q]);
        float4 w1 = __ldg(&((const float4*)W1)[1 * 32 + q]);
        float4 w2 = __ldg(&((const float4*)W1)[2 * 32 + q]);
        float4 bq = __ldg(&((const float4*)b1)[q]);
        float4 h;
        h.x = fmaxf(fmaf(v.x, w0.x, fmaf(v.y, w1.x, fmaf(v.z, w2.x, bq.x))), 0.f);
        h.y = fmaxf(fmaf(v.x, w0.y, fmaf(v.y, w1.y, fmaf(v.z, w2.y, bq.y))), 0.f);
        h.z = fmaxf(fmaf(v.x, w0.z, fmaf(v.y, w1.z, fmaf(v.z, w2.z, bq.z))), 0.f);
        h.w = fmaxf(fmaf(v.x, w0.w, fmaf(v.y, w1.w, fmaf(v.z, w2.w, bq.w))), 0.f);
        sh1[i] = h;
    }
    __syncthreads();

    int c  = tid & 15;        // cols 4c..4c+3
    int m0 = (tid >> 4) * 8;  // nodes m0..m0+7 (local)

    float4 acc[8];
    #pragma unroll
    for (int j = 0; j < 8; j++) acc[j] = make_float4(0.f, 0.f, 0.f, 0.f);

    #pragma unroll 2
    for (int kb = 0; kb < HID; kb += 4) {
        float4 w0 = sW2[(kb + 0) * 16 + c];
        float4 w1 = sW2[(kb + 1) * 16 + c];
        float4 w2 = sW2[(kb + 2) * 16 + c];
        float4 w3 = sW2[(kb + 3) * 16 + c];
        #pragma unroll
        for (int j = 0; j < 8; j++) {
            float4 h = sh1[(m0 + j) * 32 + (kb >> 2)];
            acc[j].x = fmaf(h.x, w0.x, fmaf(h.y, w1.x, fmaf(h.z, w2.x, fmaf(h.w, w3.x, acc[j].x))));
            acc[j].y = fmaf(h.x, w0.y, fmaf(h.y, w1.y, fmaf(h.z, w2.y, fmaf(h.w, w3.y, acc[j].y))));
            acc[j].z = fmaf(h.x, w0.z, fmaf(h.y, w1.z, fmaf(h.z, w2.z, fmaf(h.w, w3.z, acc[j].z))));
            acc[j].w = fmaf(h.x, w0.w, fmaf(h.y, w1.w, fmaf(h.z, w2.w, fmaf(h.w, w3.w, acc[j].w))));
        }
    }

    #pragma unroll
    for (int j = 0; j < 8; j++)
        ((float4*)g_h2)[(size_t)(nodeBase + m0 + j) * 16 + c] = acc[j];
}

// 7) layer-2 gather in 64-dim space: 16 threads per node (one float4 quad each),
//    atomic-free; folds bias + self-loop.
__global__ void k_gather2(const float* __restrict__ b2,
                          float* __restrict__ out) {
    int gid = blockIdx.x * blockDim.x + threadIdx.x;
    int node = gid >> 4;
    int q    = gid & 15;
    if (node >= N_NODES) return;
    int row = g_rowstart[node];
    int end = row + g_deg[node];
    float4 acc = make_float4(0.f, 0.f, 0.f, 0.f);
    for (int e = row; e < end; e++) {
        int s = g_csrc[e];          // broadcast within half-warp
        float w = g_dinv[s];
        float4 h = ((const float4*)g_h2)[(size_t)s * 16 + q];
        acc.x = fmaf(w, h.x, acc.x);
        acc.y = fmaf(w, h.y, acc.y);
        acc.z = fmaf(w, h.z, acc.z);
        acc.w = fmaf(w, h.w, acc.w);
    }
    float dd = g_dinv[node];
    float sl = dd * dd;
    float4 hs = ((const float4*)g_h2)[(size_t)node * 16 + q];
    float4 bb = __ldg(&((const float4*)b2)[q]);
    float4 o;
    o.x = fmaf(dd, acc.x, fmaf(sl, hs.x, bb.x));
    o.y = fmaf(dd, acc.y, fmaf(sl, hs.y, bb.y));
    o.z = fmaf(dd, acc.z, fmaf(sl, hs.z, bb.z));
    o.w = fmaf(dd, acc.w, fmaf(sl, hs.w, bb.w));
    ((float4*)out)[(size_t)node * 16 + q] = o;
}

extern "C" void kernel_launch(void* const* d_in, const int* in_sizes, int n_in,
                              void* d_out, int out_size) {
    const float* x  = (const float*)d_in[0];
    const int*   ei = (const int*)d_in[1];   // int64 in ref -> int32 on device (JAX x64 off)
    const float* W1 = (const float*)d_in[2];
    const float* b1 = (const float*)d_in[3];
    const float* W2 = (const float*)d_in[4];
    const float* b2 = (const float*)d_in[5];
    float* out = (float*)d_out;

    k_init<<<(N_NODES + 255) / 256, 256>>>();
    k_deg<<<(N_EDGES + 255) / 256, 256>>>(ei);
    k_scan1<<<SCAN_BLOCKS, 256>>>();
    k_scan2<<<1, 256>>>();
    k_scan3<<<SCAN_BLOCKS, 256>>>();
    k_csr<<<(N_EDGES + 255) / 256, 256>>>(ei);
    k_gather1<<<(N_NODES * 32 + 255) / 256, 256>>>(x);
    k_h2<<<N_PAD / 128, 256>>>(W1, b1, W2);
    k_gather2<<<(N_NODES * 16 + 255) / 256, 256>>>(b2, out);
}

// round 5
// speedup vs baseline: 1.9135x; 1.0508x over previous
#include <cuda_runtime.h>
#include <stdint.h>

#define N_NODES 50000
#define N_PAD   50048   // multiple of 128 for k_h2 tiling
#define N_EDGES 800000
#define HID     128
#define OUTC    64
#define SCAN_BLOCKS 196 // 196*256 = 50176 >= N_NODES

// ---- scratch (device globals; no allocation allowed) ----
__device__ int   g_deg[N_NODES];
__device__ int   g_rowstart[N_NODES];
__device__ int   g_wpos[N_NODES];
__device__ int   g_csrc[N_EDGES];
__device__ int   g_bsum[SCAN_BLOCKS];
__device__ float g_dinv[N_NODES];
__device__ __align__(16) float g_v[N_PAD * 4];      // layer-1 aggregated 3-vec (pad stays 0)
__device__ __align__(16) float g_h2[N_PAD * OUTC];

#define PACK2(d, lo, hi) asm("mov.b64 %0, {%1, %2};" : "=l"(d) : "f"(lo), "f"(hi))
#define UNPACK2(lo, hi, s) asm("mov.b64 {%0, %1}, %2;" : "=f"(lo), "=f"(hi) : "l"(s))
#define FMA2(d, a, b, c) asm("fma.rn.f32x2 %0, %1, %2, %3;" : "=l"(d) : "l"(a), "l"(b), "l"(c))

// 1) zero degrees
__global__ void k_init() {
    int i = blockIdx.x * blockDim.x + threadIdx.x;
    if (i < N_NODES) g_deg[i] = 0;
}

// 2) degree histogram on dst (self-loop folded analytically as +1)
__global__ void k_deg(const int* __restrict__ ei) {
    int e = blockIdx.x * blockDim.x + threadIdx.x;
    if (e >= N_EDGES) return;
    atomicAdd(&g_deg[ei[N_EDGES + e]], 1);
}

// 3a) per-block degree sums
__global__ void k_scan1() {
    __shared__ int s[256];
    int t = threadIdx.x;
    int i = blockIdx.x * 256 + t;
    s[t] = (i < N_NODES) ? g_deg[i] : 0;
    __syncthreads();
    for (int o = 128; o > 0; o >>= 1) {
        if (t < o) s[t] += s[t + o];
        __syncthreads();
    }
    if (t == 0) g_bsum[blockIdx.x] = s[0];
}

// 3b) row starts + write cursors + dinv.
//     Each block computes its own offset by reducing g_bsum[t < blockIdx.x].
__global__ void k_scan3() {
    __shared__ int s[256];
    __shared__ int sOff;
    int t = threadIdx.x;

    // block offset = sum of bsum of earlier blocks
    int bv = (t < SCAN_BLOCKS && t < (int)blockIdx.x) ? g_bsum[t] : 0;
    s[t] = bv;
    __syncthreads();
    for (int o = 128; o > 0; o >>= 1) {
        if (t < o) s[t] += s[t + o];
        __syncthreads();
    }
    if (t == 0) sOff = s[0];
    __syncthreads();

    // intra-block inclusive scan of degrees
    int i = blockIdx.x * 256 + t;
    int v = (i < N_NODES) ? g_deg[i] : 0;
    s[t] = v;
    __syncthreads();
    for (int o = 1; o < 256; o <<= 1) {
        int x = (t >= o) ? s[t - o] : 0;
        __syncthreads();
        s[t] += x;
        __syncthreads();
    }
    if (i < N_NODES) {
        int rs = sOff + s[t] - v;
        g_rowstart[i] = rs;
        g_wpos[i] = rs;
        g_dinv[i] = rsqrtf((float)(v + 1));
    }
}

// 4) CSR scatter: src indices grouped by dst
__global__ void k_csr(const int* __restrict__ ei) {
    int e = blockIdx.x * blockDim.x + threadIdx.x;
    if (e >= N_EDGES) return;
    int s = ei[e];
    int d = ei[N_EDGES + e];
    int pos = atomicAdd(&g_wpos[d], 1);
    g_csrc[pos] = s;
}

// 5) layer-1 gather in 3-dim space: warp per node, atomic-free
__global__ void k_gather1(const float* __restrict__ x) {
    int gid = blockIdx.x * blockDim.x + threadIdx.x;
    int node = gid >> 5;
    int lane = gid & 31;
    if (node >= N_NODES) return;
    int row = g_rowstart[node];
    int end = row + g_deg[node];
    float a0 = 0.f, a1 = 0.f, a2 = 0.f;
    for (int e = row + lane; e < end; e += 32) {
        int s = g_csrc[e];
        float w = g_dinv[s];
        a0 = fmaf(__ldg(&x[s * 3 + 0]), w, a0);
        a1 = fmaf(__ldg(&x[s * 3 + 1]), w, a1);
        a2 = fmaf(__ldg(&x[s * 3 + 2]), w, a2);
    }
    #pragma unroll
    for (int o = 16; o > 0; o >>= 1) {
        a0 += __shfl_down_sync(0xffffffff, a0, o);
        a1 += __shfl_down_sync(0xffffffff, a1, o);
        a2 += __shfl_down_sync(0xffffffff, a2, o);
    }
    if (lane == 0) {
        float dd = g_dinv[node];
        float sl = dd * dd;
        float4 v;
        v.x = fmaf(dd, a0, sl * __ldg(&x[node * 3 + 0]));
        v.y = fmaf(dd, a1, sl * __ldg(&x[node * 3 + 1]));
        v.z = fmaf(dd, a2, sl * __ldg(&x[node * 3 + 2]));
        v.w = 0.f;
        ((float4*)g_v)[node] = v;
    }
}

// 6) fused h1 (relu(v@W1+b1), computed into smem k-major) + h2 = h1 @ W2
//    using packed fma.rn.f32x2: accumulators packed over NODE PAIRS.
//    128 nodes/block, 256 threads; thread = (8 nodes = 4 pairs, 4 cols).
__global__ void __launch_bounds__(256) k_h2(const float* __restrict__ W1,
                                            const float* __restrict__ b1,
                                            const float* __restrict__ W2) {
    __shared__ float4 sW2[HID * 16];    // [k][16 col-quads]       32 KB
    __shared__ float  sh1T[HID * 128];  // [k][node] transposed    64 KB
    int tid = threadIdx.x;
    int nodeBase = blockIdx.x * 128;

    #pragma unroll 4
    for (int i = tid; i < HID * 16; i += 256) sW2[i] = ((const float4*)W2)[i];

    // fused h1: i -> (node = i&127, k-quad q = i>>7); writes k-major
    #pragma unroll 4
    for (int i = tid; i < 128 * 32; i += 256) {
        int node = i & 127;
        int q    = i >> 7;
        float4 v  = ((const float4*)g_v)[nodeBase + node];
        float4 w0 = __ldg(&((const float4*)W1)[0 * 32 + q]);
        float4 w1 = __ldg(&((const float4*)W1)[1 * 32 + q]);
        float4 w2 = __ldg(&((const float4*)W1)[2 * 32 + q]);
        float4 bq = __ldg(&((const float4*)b1)[q]);
        sh1T[(4 * q + 0) * 128 + node] = fmaxf(fmaf(v.x, w0.x, fmaf(v.y, w1.x, fmaf(v.z, w2.x, bq.x))), 0.f);
        sh1T[(4 * q + 1) * 128 + node] = fmaxf(fmaf(v.x, w0.y, fmaf(v.y, w1.y, fmaf(v.z, w2.y, bq.y))), 0.f);
        sh1T[(4 * q + 2) * 128 + node] = fmaxf(fmaf(v.x, w0.z, fmaf(v.y, w1.z, fmaf(v.z, w2.z, bq.z))), 0.f);
        sh1T[(4 * q + 3) * 128 + node] = fmaxf(fmaf(v.x, w0.w, fmaf(v.y, w1.w, fmaf(v.z, w2.w, bq.w))), 0.f);
    }
    __syncthreads();

    int c  = tid & 15;        // cols 4c..4c+3
    int m0 = (tid >> 4) * 8;  // nodes m0..m0+7 (4 packed pairs)

    // acc[p][cc]: lanes = (node m0+2p, m0+2p+1), col 4c+cc
    unsigned long long acc[4][4];
    #pragma unroll
    for (int p = 0; p < 4; p++)
        #pragma unroll
        for (int cc = 0; cc < 4; cc++) acc[p][cc] = 0ull;

    #pragma unroll 2
    for (int kb = 0; kb < HID; kb += 4) {
        #pragma unroll
        for (int kk = 0; kk < 4; kk++) {
            int k = kb + kk;
            float4 w = sW2[k * 16 + c];
            unsigned long long wp[4];
            PACK2(wp[0], w.x, w.x);
            PACK2(wp[1], w.y, w.y);
            PACK2(wp[2], w.z, w.z);
            PACK2(wp[3], w.w, w.w);
            float4 ha = *(const float4*)&sh1T[k * 128 + m0];
            float4 hb = *(const float4*)&sh1T[k * 128 + m0 + 4];
            unsigned long long hp[4];
            PACK2(hp[0], ha.x, ha.y);
            PACK2(hp[1], ha.z, ha.w);
            PACK2(hp[2], hb.x, hb.y);
            PACK2(hp[3], hb.z, hb.w);
            #pragma unroll
            for (int p = 0; p < 4; p++) {
                FMA2(acc[p][0], hp[p], wp[0], acc[p][0]);
                FMA2(acc[p][1], hp[p], wp[1], acc[p][1]);
                FMA2(acc[p][2], hp[p], wp[2], acc[p][2]);
                FMA2(acc[p][3], hp[p], wp[3], acc[p][3]);
            }
        }
    }

    #pragma unroll
    for (int p = 0; p < 4; p++) {
        float4 r0, r1;
        UNPACK2(r0.x, r1.x, acc[p][0]);
        UNPACK2(r0.y, r1.y, acc[p][1]);
        UNPACK2(r0.z, r1.z, acc[p][2]);
        UNPACK2(r0.w, r1.w, acc[p][3]);
        int n0 = nodeBase + m0 + 2 * p;
        ((float4*)g_h2)[(size_t)n0 * 16 + c] = r0;
        ((float4*)g_h2)[(size_t)(n0 + 1) * 16 + c] = r1;
    }
}

// 7) layer-2 gather in 64-dim space: 16 threads per node (one float4 quad each),
//    atomic-free; folds bias + self-loop. Unrolled x2 for MLP.
__global__ void k_gather2(const float* __restrict__ b2,
                          float* __restrict__ out) {
    int gid = blockIdx.x * blockDim.x + threadIdx.x;
    int node = gid >> 4;
    int q    = gid & 15;
    if (node >= N_NODES) return;
    int row = g_rowstart[node];
    int end = row + g_deg[node];
    float4 acc = make_float4(0.f, 0.f, 0.f, 0.f);
    int e = row;
    for (; e + 2 <= end; e += 2) {
        int s0 = g_csrc[e];
        int s1 = g_csrc[e + 1];
        float w0 = g_dinv[s0];
        float w1 = g_dinv[s1];
        float4 h0 = ((const float4*)g_h2)[(size_t)s0 * 16 + q];
        float4 h1 = ((const float4*)g_h2)[(size_t)s1 * 16 + q];
        acc.x = fmaf(w0, h0.x, fmaf(w1, h1.x, acc.x));
        acc.y = fmaf(w0, h0.y, fmaf(w1, h1.y, acc.y));
        acc.z = fmaf(w0, h0.z, fmaf(w1, h1.z, acc.z));
        acc.w = fmaf(w0, h0.w, fmaf(w1, h1.w, acc.w));
    }
    if (e < end) {
        int s = g_csrc[e];
        float w = g_dinv[s];
        float4 h = ((const float4*)g_h2)[(size_t)s * 16 + q];
        acc.x = fmaf(w, h.x, acc.x);
        acc.y = fmaf(w, h.y, acc.y);
        acc.z = fmaf(w, h.z, acc.z);
        acc.w = fmaf(w, h.w, acc.w);
    }
    float dd = g_dinv[node];
    float sl = dd * dd;
    float4 hs = ((const float4*)g_h2)[(size_t)node * 16 + q];
    float4 bb = __ldg(&((const float4*)b2)[q]);
    float4 o;
    o.x = fmaf(dd, acc.x, fmaf(sl, hs.x, bb.x));
    o.y = fmaf(dd, acc.y, fmaf(sl, hs.y, bb.y));
    o.z = fmaf(dd, acc.z, fmaf(sl, hs.z, bb.z));
    o.w = fmaf(dd, acc.w, fmaf(sl, hs.w, bb.w));
    ((float4*)out)[(size_t)node * 16 + q] = o;
}

extern "C" void kernel_launch(void* const* d_in, const int* in_sizes, int n_in,
                              void* d_out, int out_size) {
    const float* x  = (const float*)d_in[0];
    const int*   ei = (const int*)d_in[1];   // int64 in ref -> int32 on device (JAX x64 off)
    const float* W1 = (const float*)d_in[2];
    const float* b1 = (const float*)d_in[3];
    const float* W2 = (const float*)d_in[4];
    const float* b2 = (const float*)d_in[5];
    float* out = (float*)d_out;

    k_init<<<(N_NODES + 255) / 256, 256>>>();
    k_deg<<<(N_EDGES + 255) / 256, 256>>>(ei);
    k_scan1<<<SCAN_BLOCKS, 256>>>();
    k_scan3<<<SCAN_BLOCKS, 256>>>();
    k_csr<<<(N_EDGES + 255) / 256, 256>>>(ei);
    k_gather1<<<(N_NODES * 32 + 255) / 256, 256>>>(x);
    k_h2<<<N_PAD / 128, 256>>>(W1, b1, W2);
    k_gather2<<<(N_NODES * 16 + 255) / 256, 256>>>(b2, out);
}

// round 6
// speedup vs baseline: 1.9706x; 1.0298x over previous
#include <cuda_runtime.h>
#include <stdint.h>

#define N_NODES 50000
#define N_PAD   50048   // multiple of 128 for k_h2 tiling
#define N_EDGES 800000
#define HID     128
#define OUTC    64

// ---- scratch (device globals; no allocation allowed) ----
__device__ int   g_deg[N_NODES];
__device__ int   g_rowstart[N_NODES];
__device__ int   g_wpos[N_NODES];
__device__ int   g_csrc[N_EDGES];
__device__ int   g_total;
__device__ float g_dinv[N_NODES];
__device__ __align__(16) float g_v[N_PAD * 4];      // layer-1 aggregated 3-vec (pad stays 0)
__device__ __align__(16) float g_h2[N_PAD * OUTC];

#define PACK2(d, lo, hi) asm("mov.b64 %0, {%1, %2};" : "=l"(d) : "f"(lo), "f"(hi))
#define UNPACK2(lo, hi, s) asm("mov.b64 {%0, %1}, %2;" : "=f"(lo), "=f"(hi) : "l"(s))
#define FMA2(d, a, b, c) asm("fma.rn.f32x2 %0, %1, %2, %3;" : "=l"(d) : "l"(a), "l"(b), "l"(c))

// 1) zero degrees + cursor
__global__ void k_init() {
    int i = blockIdx.x * blockDim.x + threadIdx.x;
    if (i < N_NODES) g_deg[i] = 0;
    if (i == 0) g_total = 0;
}

// 2) degree histogram on dst (self-loop folded analytically as +1); 2 edges/thread
__global__ void k_deg(const int* __restrict__ ei) {
    int e2 = blockIdx.x * blockDim.x + threadIdx.x;
    if (e2 >= N_EDGES / 2) return;
    int2 d = ((const int2*)(ei + N_EDGES))[e2];
    atomicAdd(&g_deg[d.x], 1);
    atomicAdd(&g_deg[d.y], 1);
}

// 3) row allocation: warp-shuffle scan + one atomic per warp (order-free CSR rows)
__global__ void k_assign() {
    int i = blockIdx.x * blockDim.x + threadIdx.x;
    int lane = threadIdx.x & 31;
    int deg = (i < N_NODES) ? g_deg[i] : 0;
    int incl = deg;
    #pragma unroll
    for (int o = 1; o < 32; o <<= 1) {
        int v = __shfl_up_sync(0xffffffff, incl, o);
        if (lane >= o) incl += v;
    }
    int base = 0;
    if (lane == 31) base = atomicAdd(&g_total, incl);   // incl@31 = warp total
    base = __shfl_sync(0xffffffff, base, 31);
    if (i < N_NODES) {
        int rs = base + incl - deg;
        g_rowstart[i] = rs;
        g_wpos[i] = rs;
        g_dinv[i] = rsqrtf((float)(deg + 1));
    }
}

// 4) CSR scatter: src indices grouped by dst; 2 edges/thread
__global__ void k_csr(const int* __restrict__ ei) {
    int e2 = blockIdx.x * blockDim.x + threadIdx.x;
    if (e2 >= N_EDGES / 2) return;
    int2 s = ((const int2*)ei)[e2];
    int2 d = ((const int2*)(ei + N_EDGES))[e2];
    int p0 = atomicAdd(&g_wpos[d.x], 1);
    g_csrc[p0] = s.x;
    int p1 = atomicAdd(&g_wpos[d.y], 1);
    g_csrc[p1] = s.y;
}

// 5) layer-1 gather in 3-dim space: warp per node, atomic-free
__global__ void k_gather1(const float* __restrict__ x) {
    int gid = blockIdx.x * blockDim.x + threadIdx.x;
    int node = gid >> 5;
    int lane = gid & 31;
    if (node >= N_NODES) return;
    int row = g_rowstart[node];
    int end = row + g_deg[node];
    float a0 = 0.f, a1 = 0.f, a2 = 0.f;
    for (int e = row + lane; e < end; e += 32) {
        int s = g_csrc[e];
        float w = g_dinv[s];
        a0 = fmaf(__ldg(&x[s * 3 + 0]), w, a0);
        a1 = fmaf(__ldg(&x[s * 3 + 1]), w, a1);
        a2 = fmaf(__ldg(&x[s * 3 + 2]), w, a2);
    }
    #pragma unroll
    for (int o = 16; o > 0; o >>= 1) {
        a0 += __shfl_down_sync(0xffffffff, a0, o);
        a1 += __shfl_down_sync(0xffffffff, a1, o);
        a2 += __shfl_down_sync(0xffffffff, a2, o);
    }
    if (lane == 0) {
        float dd = g_dinv[node];
        float sl = dd * dd;
        float4 v;
        v.x = fmaf(dd, a0, sl * __ldg(&x[node * 3 + 0]));
        v.y = fmaf(dd, a1, sl * __ldg(&x[node * 3 + 1]));
        v.z = fmaf(dd, a2, sl * __ldg(&x[node * 3 + 2]));
        v.w = 0.f;
        ((float4*)g_v)[node] = v;
    }
}

// 6) fused h1 (relu(v@W1+b1), smem k-major) + h2 = h1 @ W2 with fma.rn.f32x2
//    128 nodes/block, 256 threads; thread = (8 nodes = 4 node-pairs, 4 cols).
__global__ void __launch_bounds__(256) k_h2(const float* __restrict__ W1,
                                            const float* __restrict__ b1,
                                            const float* __restrict__ W2) {
    __shared__ float4 sW2[HID * 16];    // [k][16 col-quads]       32 KB
    __shared__ float  sh1T[HID * 128];  // [k][node] transposed    64 KB
    int tid = threadIdx.x;
    int nodeBase = blockIdx.x * 128;

    #pragma unroll 4
    for (int i = tid; i < HID * 16; i += 256) sW2[i] = ((const float4*)W2)[i];

    #pragma unroll 4
    for (int i = tid; i < 128 * 32; i += 256) {
        int node = i & 127;
        int q    = i >> 7;
        float4 v  = ((const float4*)g_v)[nodeBase + node];
        float4 w0 = __ldg(&((const float4*)W1)[0 * 32 + q]);
        float4 w1 = __ldg(&((const float4*)W1)[1 * 32 + q]);
        float4 w2 = __ldg(&((const float4*)W1)[2 * 32 + q]);
        float4 bq = __ldg(&((const float4*)b1)[q]);
        sh1T[(4 * q + 0) * 128 + node] = fmaxf(fmaf(v.x, w0.x, fmaf(v.y, w1.x, fmaf(v.z, w2.x, bq.x))), 0.f);
        sh1T[(4 * q + 1) * 128 + node] = fmaxf(fmaf(v.x, w0.y, fmaf(v.y, w1.y, fmaf(v.z, w2.y, bq.y))), 0.f);
        sh1T[(4 * q + 2) * 128 + node] = fmaxf(fmaf(v.x, w0.z, fmaf(v.y, w1.z, fmaf(v.z, w2.z, bq.z))), 0.f);
        sh1T[(4 * q + 3) * 128 + node] = fmaxf(fmaf(v.x, w0.w, fmaf(v.y, w1.w, fmaf(v.z, w2.w, bq.w))), 0.f);
    }
    __syncthreads();

    int c  = tid & 15;        // cols 4c..4c+3
    int m0 = (tid >> 4) * 8;  // nodes m0..m0+7 (4 packed pairs)

    unsigned long long acc[4][4];
    #pragma unroll
    for (int p = 0; p < 4; p++)
        #pragma unroll
        for (int cc = 0; cc < 4; cc++) acc[p][cc] = 0ull;

    #pragma unroll 2
    for (int kb = 0; kb < HID; kb += 4) {
        #pragma unroll
        for (int kk = 0; kk < 4; kk++) {
            int k = kb + kk;
            float4 w = sW2[k * 16 + c];
            unsigned long long wp[4];
            PACK2(wp[0], w.x, w.x);
            PACK2(wp[1], w.y, w.y);
            PACK2(wp[2], w.z, w.z);
            PACK2(wp[3], w.w, w.w);
            float4 ha = *(const float4*)&sh1T[k * 128 + m0];
            float4 hb = *(const float4*)&sh1T[k * 128 + m0 + 4];
            unsigned long long hp[4];
            PACK2(hp[0], ha.x, ha.y);
            PACK2(hp[1], ha.z, ha.w);
            PACK2(hp[2], hb.x, hb.y);
            PACK2(hp[3], hb.z, hb.w);
            #pragma unroll
            for (int p = 0; p < 4; p++) {
                FMA2(acc[p][0], hp[p], wp[0], acc[p][0]);
                FMA2(acc[p][1], hp[p], wp[1], acc[p][1]);
                FMA2(acc[p][2], hp[p], wp[2], acc[p][2]);
                FMA2(acc[p][3], hp[p], wp[3], acc[p][3]);
            }
        }
    }

    #pragma unroll
    for (int p = 0; p < 4; p++) {
        float4 r0, r1;
        UNPACK2(r0.x, r1.x, acc[p][0]);
        UNPACK2(r0.y, r1.y, acc[p][1]);
        UNPACK2(r0.z, r1.z, acc[p][2]);
        UNPACK2(r0.w, r1.w, acc[p][3]);
        int n0 = nodeBase + m0 + 2 * p;
        ((float4*)g_h2)[(size_t)n0 * 16 + c] = r0;
        ((float4*)g_h2)[(size_t)(n0 + 1) * 16 + c] = r1;
    }
}

// 7) layer-2 gather, 16 threads/node (one float4 quad each), unroll x4
__global__ void k_gather2(const float* __restrict__ b2,
                          float* __restrict__ out) {
    int gid = blockIdx.x * blockDim.x + threadIdx.x;
    int node = gid >> 4;
    int q    = gid & 15;
    if (node >= N_NODES) return;
    int row = g_rowstart[node];
    int end = row + g_deg[node];
    float4 acc = make_float4(0.f, 0.f, 0.f, 0.f);
    int e = row;
    for (; e + 4 <= end; e += 4) {
        int s0 = g_csrc[e];
        int s1 = g_csrc[e + 1];
        int s2 = g_csrc[e + 2];
        int s3 = g_csrc[e + 3];
        float w0 = g_dinv[s0];
        float w1 = g_dinv[s1];
        float w2 = g_dinv[s2];
        float w3 = g_dinv[s3];
        float4 h0 = ((const float4*)g_h2)[(size_t)s0 * 16 + q];
        float4 h1 = ((const float4*)g_h2)[(size_t)s1 * 16 + q];
        float4 h2 = ((const float4*)g_h2)[(size_t)s2 * 16 + q];
        float4 h3 = ((const float4*)g_h2)[(size_t)s3 * 16 + q];
        acc.x = fmaf(w0, h0.x, fmaf(w1, h1.x, fmaf(w2, h2.x, fmaf(w3, h3.x, acc.x))));
        acc.y = fmaf(w0, h0.y, fmaf(w1, h1.y, fmaf(w2, h2.y, fmaf(w3, h3.y, acc.y))));
        acc.z = fmaf(w0, h0.z, fmaf(w1, h1.z, fmaf(w2, h2.z, fmaf(w3, h3.z, acc.z))));
        acc.w = fmaf(w0, h0.w, fmaf(w1, h1.w, fmaf(w2, h2.w, fmaf(w3, h3.w, acc.w))));
    }
    for (; e < end; e++) {
        int s = g_csrc[e];
        float w = g_dinv[s];
        float4 h = ((const float4*)g_h2)[(size_t)s * 16 + q];
        acc.x = fmaf(w, h.x, acc.x);
        acc.y = fmaf(w, h.y, acc.y);
        acc.z = fmaf(w, h.z, acc.z);
        acc.w = fmaf(w, h.w, acc.w);
    }
    float dd = g_dinv[node];
    float sl = dd * dd;
    float4 hs = ((const float4*)g_h2)[(size_t)node * 16 + q];
    float4 bb = __ldg(&((const float4*)b2)[q]);
    float4 o;
    o.x = fmaf(dd, acc.x, fmaf(sl, hs.x, bb.x));
    o.y = fmaf(dd, acc.y, fmaf(sl, hs.y, bb.y));
    o.z = fmaf(dd, acc.z, fmaf(sl, hs.z, bb.z));
    o.w = fmaf(dd, acc.w, fmaf(sl, hs.w, bb.w));
    ((float4*)out)[(size_t)node * 16 + q] = o;
}

extern "C" void kernel_launch(void* const* d_in, const int* in_sizes, int n_in,
                              void* d_out, int out_size) {
    const float* x  = (const float*)d_in[0];
    const int*   ei = (const int*)d_in[1];   // int64 in ref -> int32 on device (JAX x64 off)
    const float* W1 = (const float*)d_in[2];
    const float* b1 = (const float*)d_in[3];
    const float* W2 = (const float*)d_in[4];
    const float* b2 = (const float*)d_in[5];
    float* out = (float*)d_out;

    k_init<<<(N_NODES + 255) / 256, 256>>>();
    k_deg<<<(N_EDGES / 2 + 255) / 256, 256>>>(ei);
    k_assign<<<(N_NODES + 255) / 256, 256>>>();
    k_csr<<<(N_EDGES / 2 + 255) / 256, 256>>>(ei);
    k_gather1<<<(N_NODES * 32 + 255) / 256, 256>>>(x);
    k_h2<<<N_PAD / 128, 256>>>(W1, b1, W2);
    k_gather2<<<(N_NODES * 16 + 255) / 256, 256>>>(b2, out);
}